// round 13
// baseline (speedup 1.0000x reference)
#include <cuda_runtime.h>
#include <cuda_bf16.h>
#include <cstdint>
#include <cstddef>

#define NN     50000
#define NE     800000
#define INC    128
#define HID    64
#define HEADS  4
#define D1     256          // HEADS*HID
#define OUTC   10
#define NG     500
#define NEG    0.2f

// ---------------- scratch (device globals; allocation-free) ----------------
__device__ __align__(16) __nv_bfloat16 g_h1b [NN * D1];   // x @ W1    (bf16)
__device__ __align__(16) __nv_bfloat16 g_out1b[NN * D1];  // relu(GAT1+b1) bf16
__device__ __align__(16) __nv_bfloat16 g_h2b [NN * HID];  // out1 @ W2 (bf16)
__device__ __align__(16) float g_als1[NN * HEADS];
__device__ __align__(16) float g_ald1[NN * HEADS];
__device__ float g_als2[NN], g_ald2[NN];
__device__ __align__(16) float g_pool[NG * HID];

// index handling + CSR (dst-sorted)
__device__ int g_is64;
__device__ int g_src[NE];
__device__ int g_dst[NE];
__device__ int g_bat[NN];
__device__ int g_deg[NN];
__device__ int g_row[NN + 1];
__device__ int g_cur[NN];
__device__ int g_csr_src[NE];

// ---------------- helpers ----------------
__device__ __forceinline__ float leaky(float v) { return v > 0.f ? v : NEG * v; }

__device__ __forceinline__ void red4(float* p, float4 v) {
    asm volatile("red.global.add.v4.f32 [%0], {%1,%2,%3,%4};"
                 :: "l"(p), "f"(v.x), "f"(v.y), "f"(v.z), "f"(v.w) : "memory");
}

__device__ __forceinline__ void unp8(uint4 u, float* f) {
    float2 p;
    p = __bfloat1622float2(*(const __nv_bfloat162*)&u.x); f[0] = p.x; f[1] = p.y;
    p = __bfloat1622float2(*(const __nv_bfloat162*)&u.y); f[2] = p.x; f[3] = p.y;
    p = __bfloat1622float2(*(const __nv_bfloat162*)&u.z); f[4] = p.x; f[5] = p.y;
    p = __bfloat1622float2(*(const __nv_bfloat162*)&u.w); f[6] = p.x; f[7] = p.y;
}

__device__ __forceinline__ unsigned f2tf(float f) {
    unsigned u;
    asm("cvt.rna.tf32.f32 %0, %1;" : "=r"(u) : "f"(f));
    return u;
}

// ------- prep: detect index dtype + zero degree array + zero pool ----------
__global__ void prep_k(const int* __restrict__ raw) {
    int n = blockIdx.x * blockDim.x + threadIdx.x;
    if (n < NN) g_deg[n] = 0;
    if (n < NG * HID) g_pool[n] = 0.f;
    if (n == 0) {
        int acc = 0;
#pragma unroll 1
        for (int i = 1; i < 128; i += 2) acc |= raw[i];
        g_is64 = (acc == 0) ? 1 : 0;   // int64 LE: high words all zero
    }
}

__global__ void cvt_k(const int* __restrict__ eraw, const int* __restrict__ braw) {
    int e = blockIdx.x * blockDim.x + threadIdx.x;
    if (e >= NE) return;
    int s, d;
    if (g_is64) {
        const long long* p = (const long long*)eraw;
        s = (int)p[e];
        d = (int)p[(size_t)NE + e];
        if (e < NN) g_bat[e] = (int)((const long long*)braw)[e];
    } else {
        s = eraw[e];
        d = eraw[NE + e];
        if (e < NN) g_bat[e] = braw[e];
    }
    g_src[e] = s;
    g_dst[e] = d;
    atomicAdd(&g_deg[d], 1);
}

// single-block exclusive scan over g_deg -> g_row; inits g_cur
__global__ __launch_bounds__(1024) void scan_k() {
    __shared__ int wsum[32];
    __shared__ int s_carry;
    const int tid = threadIdx.x, lane = tid & 31, wid = tid >> 5;
    if (tid == 0) s_carry = 0;
    __syncthreads();
    for (int base = 0; base < NN; base += 1024) {
        int i = base + tid;
        int v = (i < NN) ? g_deg[i] : 0;
        int incl = v;
#pragma unroll
        for (int off = 1; off < 32; off <<= 1) {
            int t = __shfl_up_sync(0xFFFFFFFFu, incl, off);
            if (lane >= off) incl += t;
        }
        if (lane == 31) wsum[wid] = incl;
        __syncthreads();
        if (wid == 0) {
            int w = wsum[lane];
            int wi = w;
#pragma unroll
            for (int off = 1; off < 32; off <<= 1) {
                int t = __shfl_up_sync(0xFFFFFFFFu, wi, off);
                if (lane >= off) wi += t;
            }
            wsum[lane] = wi - w;
        }
        __syncthreads();
        int c = s_carry;
        int excl = c + wsum[wid] + incl - v;
        if (i < NN) {
            g_row[i] = excl;
            g_cur[i] = excl;
        }
        __syncthreads();
        if (tid == 1023) s_carry = c + wsum[31] + incl;
        __syncthreads();
    }
    if (tid == 0) g_row[NN] = s_carry;
}

__global__ void place_k() {
    int e = blockIdx.x * blockDim.x + threadIdx.x;
    if (e >= NE) return;
    int p = atomicAdd(&g_cur[g_dst[e]], 1);
    g_csr_src[p] = g_src[e];
}

// ---- tf32 tensor-core GEMM + fused attention-logit epilogue --------------
// C_bf16[M,N] = A[M,K] @ B[K,N]; BM=128, BN=64, BK=16; 256 threads, 8 warps
// (4m x 2n), warp tile 32x32. A fp32 (AB16=0) or bf16 (AB16=1).
// Epilogue: block (bx = head) covers the FULL 64-col feature dim of that head,
// so als/ald = <C_row, a_src/a_dst> reduce entirely in-block (no atomics).
template<int AB16>
__global__ __launch_bounds__(256) void mma_gemm_k(const void* __restrict__ Av,
                                                  const float* __restrict__ B,
                                                  __nv_bfloat16* __restrict__ C,
                                                  const float* __restrict__ avs,
                                                  const float* __restrict__ avd,
                                                  float* __restrict__ gals,
                                                  float* __restrict__ gald,
                                                  int hstride,
                                                  int M, int N, int K) {
    constexpr int BM = 128, BN = 64, BK = 16;
    __shared__ unsigned As[BM][BK + 4];
    __shared__ unsigned Bs[BK][BN + 8];
    __shared__ float s_als[BM], s_ald[BM];
    const int tid = threadIdx.x;
    const int lane = tid & 31, w = tid >> 5;
    const int wm = (w & 3) * 32, wn = (w >> 2) * 32;
    const int g = lane >> 2, tg = lane & 3;
    const int m0 = blockIdx.y * BM, n0 = blockIdx.x * BN;

    float c[2][4][4];
#pragma unroll
    for (int mt = 0; mt < 2; mt++)
#pragma unroll
        for (int nt = 0; nt < 4; nt++)
#pragma unroll
            for (int r = 0; r < 4; r++) c[mt][nt][r] = 0.f;

    for (int kb = 0; kb < K; kb += BK) {
        if (AB16) {   // A tile 128x16 bf16: 1 uint4 (8 elems) per thread
            const __nv_bfloat16* A = (const __nv_bfloat16*)Av;
            int row = tid >> 1, c8 = (tid & 1) * 8;
            float f[8] = {0.f, 0.f, 0.f, 0.f, 0.f, 0.f, 0.f, 0.f};
            if (m0 + row < M)
                unp8(*(const uint4*)(A + (size_t)(m0 + row) * K + kb + c8), f);
#pragma unroll
            for (int j = 0; j < 8; j++) As[row][c8 + j] = f2tf(f[j]);
        } else {      // A tile 128x16 fp32: 2 float4 per thread
            const float* A = (const float*)Av;
            int row = tid >> 2, c4 = (tid & 3) * 4;
#pragma unroll
            for (int r = 0; r < 2; r++) {
                int rr = row + r * 64;
                float4 f = make_float4(0.f, 0.f, 0.f, 0.f);
                if (m0 + rr < M) f = *(const float4*)(A + (size_t)(m0 + rr) * K + kb + c4);
                As[rr][c4 + 0] = f2tf(f.x); As[rr][c4 + 1] = f2tf(f.y);
                As[rr][c4 + 2] = f2tf(f.z); As[rr][c4 + 3] = f2tf(f.w);
            }
        }
        {   // B tile 16x64: 1 float4 per thread
            int row = tid >> 4, c4 = (tid & 15) * 4;
            float4 f = *(const float4*)(B + (size_t)(kb + row) * N + n0 + c4);
            Bs[row][c4 + 0] = f2tf(f.x); Bs[row][c4 + 1] = f2tf(f.y);
            Bs[row][c4 + 2] = f2tf(f.z); Bs[row][c4 + 3] = f2tf(f.w);
        }
        __syncthreads();
#pragma unroll
        for (int kk = 0; kk < 2; kk++) {
            const int k0 = kk * 8;
            unsigned a[2][4], b[4][2];
#pragma unroll
            for (int mt = 0; mt < 2; mt++) {
                int r = wm + mt * 16;
                a[mt][0] = As[r + g][k0 + tg];
                a[mt][1] = As[r + g + 8][k0 + tg];
                a[mt][2] = As[r + g][k0 + tg + 4];
                a[mt][3] = As[r + g + 8][k0 + tg + 4];
            }
#pragma unroll
            for (int nt = 0; nt < 4; nt++) {
                int cc = wn + nt * 8 + g;
                b[nt][0] = Bs[k0 + tg][cc];
                b[nt][1] = Bs[k0 + tg + 4][cc];
            }
#pragma unroll
            for (int mt = 0; mt < 2; mt++)
#pragma unroll
                for (int nt = 0; nt < 4; nt++) {
                    asm volatile(
                        "mma.sync.aligned.m16n8k8.row.col.f32.tf32.tf32.f32 "
                        "{%0,%1,%2,%3}, {%4,%5,%6,%7}, {%8,%9}, {%0,%1,%2,%3};"
                        : "+f"(c[mt][nt][0]), "+f"(c[mt][nt][1]),
                          "+f"(c[mt][nt][2]), "+f"(c[mt][nt][3])
                        : "r"(a[mt][0]), "r"(a[mt][1]), "r"(a[mt][2]), "r"(a[mt][3]),
                          "r"(b[nt][0]), "r"(b[nt][1]));
                }
        }
        __syncthreads();
    }

    // store C (bf16)
#pragma unroll
    for (int mt = 0; mt < 2; mt++)
#pragma unroll
        for (int nt = 0; nt < 4; nt++) {
            int row0 = m0 + wm + mt * 16 + g;
            int col = n0 + wn + nt * 8 + tg * 2;
            if (row0 < M)
                *(__nv_bfloat162*)(C + (size_t)row0 * N + col) =
                    __floats2bfloat162_rn(c[mt][nt][0], c[mt][nt][1]);
            if (row0 + 8 < M)
                *(__nv_bfloat162*)(C + (size_t)(row0 + 8) * N + col) =
                    __floats2bfloat162_rn(c[mt][nt][2], c[mt][nt][3]);
        }

    // ---- fused attention-logit epilogue ----
    const float* av = avs + blockIdx.x * BN;   // head = blockIdx.x
    const float* bv = avd + blockIdx.x * BN;
    float pals[4] = {0.f, 0.f, 0.f, 0.f}, pald[4] = {0.f, 0.f, 0.f, 0.f};
#pragma unroll
    for (int mt = 0; mt < 2; mt++)
#pragma unroll
        for (int nt = 0; nt < 4; nt++) {
            int col = wn + nt * 8 + tg * 2;
            float as0 = av[col], as1 = av[col + 1];
            float ad0 = bv[col], ad1 = bv[col + 1];
            pals[mt * 2 + 0] += c[mt][nt][0] * as0 + c[mt][nt][1] * as1;
            pals[mt * 2 + 1] += c[mt][nt][2] * as0 + c[mt][nt][3] * as1;
            pald[mt * 2 + 0] += c[mt][nt][0] * ad0 + c[mt][nt][1] * ad1;
            pald[mt * 2 + 1] += c[mt][nt][2] * ad0 + c[mt][nt][3] * ad1;
        }
    // reduce across the tg quad (lanes g*4 .. g*4+3)
#pragma unroll
    for (int off = 1; off < 4; off <<= 1)
#pragma unroll
        for (int r = 0; r < 4; r++) {
            pals[r] += __shfl_xor_sync(0xFFFFFFFFu, pals[r], off);
            pald[r] += __shfl_xor_sync(0xFFFFFFFFu, pald[r], off);
        }
    // pals[r] ~ local row wm + r*8 + g; combine the two wn halves via smem
    if (w >= 4 && tg == 0) {
#pragma unroll
        for (int r = 0; r < 4; r++) {
            int lr = wm + r * 8 + g;
            s_als[lr] = pals[r];
            s_ald[lr] = pald[r];
        }
    }
    __syncthreads();
    if (w < 4 && tg == 0) {
#pragma unroll
        for (int r = 0; r < 4; r++) {
            int lr = wm + r * 8 + g;
            int grow = m0 + lr;
            if (grow < M) {
                gals[grow * hstride + blockIdx.x] = pals[r] + s_als[lr];
                gald[grow * hstride + blockIdx.x] = pald[r] + s_ald[lr];
            }
        }
    }
}

// ------- layer 1: fused single-pass softmax + aggregate + bias + relu -------
// warp per dst node; lane owns channels [lane*8, lane*8+8), head h = lane>>3
__global__ __launch_bounds__(256) void agg1_k(const float* __restrict__ b1) {
    int node = (blockIdx.x * blockDim.x + threadIdx.x) >> 5;
    int lane = threadIdx.x & 31;
    if (node >= NN) return;
    const int h = lane >> 3;
    const int beg = g_row[node], end = g_row[node + 1];

    const float ald = g_ald1[node * 4 + h];
    float ex = __expf(leaky(g_als1[node * 4 + h] + ald));  // self-loop term
    float den = ex;
    float acc[8];
    {
        float f[8];
        unp8(*(const uint4*)(g_h1b + (size_t)node * D1 + lane * 8), f);
#pragma unroll
        for (int c = 0; c < 8; c++) acc[c] = ex * f[c];
    }
    for (int i = beg; i < end; i++) {
        int s = g_csr_src[i];
        float w = __expf(leaky(g_als1[s * 4 + h] + ald));
        den += w;
        float f[8];
        unp8(*(const uint4*)(g_h1b + (size_t)s * D1 + lane * 8), f);
#pragma unroll
        for (int c = 0; c < 8; c++) acc[c] = fmaf(w, f[c], acc[c]);
    }
    float inv = 1.f / (den + 1e-16f);
    const float4* bp = (const float4*)(b1 + lane * 8);
    float4 b0 = bp[0], b4 = bp[1];
    float o[8];
    o[0] = fmaxf(fmaf(acc[0], inv, b0.x), 0.f);
    o[1] = fmaxf(fmaf(acc[1], inv, b0.y), 0.f);
    o[2] = fmaxf(fmaf(acc[2], inv, b0.z), 0.f);
    o[3] = fmaxf(fmaf(acc[3], inv, b0.w), 0.f);
    o[4] = fmaxf(fmaf(acc[4], inv, b4.x), 0.f);
    o[5] = fmaxf(fmaf(acc[5], inv, b4.y), 0.f);
    o[6] = fmaxf(fmaf(acc[6], inv, b4.z), 0.f);
    o[7] = fmaxf(fmaf(acc[7], inv, b4.w), 0.f);
    uint4 pk;
    *(__nv_bfloat162*)&pk.x = __floats2bfloat162_rn(o[0], o[1]);
    *(__nv_bfloat162*)&pk.y = __floats2bfloat162_rn(o[2], o[3]);
    *(__nv_bfloat162*)&pk.z = __floats2bfloat162_rn(o[4], o[5]);
    *(__nv_bfloat162*)&pk.w = __floats2bfloat162_rn(o[6], o[7]);
    *(uint4*)(g_out1b + (size_t)node * D1 + lane * 8) = pk;
}

// ------- layer 2: fused single-pass softmax + aggregate + bias + pool -------
__global__ __launch_bounds__(256) void agg2_k(const float* __restrict__ b2) {
    int node = (blockIdx.x * blockDim.x + threadIdx.x) >> 5;
    int lane = threadIdx.x & 31;
    if (node >= NN) return;
    const int beg = g_row[node], end = g_row[node + 1];

    const float ald = g_ald2[node];
    float ex = __expf(leaky(g_als2[node] + ald));
    float den = ex;
    float a0, a1;
    {
        float2 v = __bfloat1622float2(
            *(const __nv_bfloat162*)(g_h2b + (size_t)node * HID + lane * 2));
        a0 = ex * v.x; a1 = ex * v.y;
    }
    for (int i = beg; i < end; i++) {
        int s = g_csr_src[i];
        float w = __expf(leaky(g_als2[s] + ald));
        den += w;
        float2 v = __bfloat1622float2(
            *(const __nv_bfloat162*)(g_h2b + (size_t)s * HID + lane * 2));
        a0 = fmaf(w, v.x, a0);
        a1 = fmaf(w, v.y, a1);
    }
    float inv = 1.f / (den + 1e-16f);
    float2 bb = *(const float2*)(b2 + lane * 2);
    float v0 = fmaf(a0, inv, bb.x);
    float v1 = fmaf(a1, inv, bb.y);

    float u0 = __shfl_down_sync(0xFFFFFFFFu, v0, 1);
    float u1 = __shfl_down_sync(0xFFFFFFFFu, v1, 1);
    if ((lane & 1) == 0) {
        int g = g_bat[node];
        red4(&g_pool[g * HID + lane * 2], make_float4(v0, v1, u0, u1));
    }
}

// ---------------- classifier ----------------
__global__ void cls_k(const float* __restrict__ fcw, const float* __restrict__ fcb,
                      float* __restrict__ out) {
    int g = blockIdx.x * blockDim.x + threadIdx.x;
    if (g >= NG) return;
    float l[OUTC];
#pragma unroll
    for (int j = 0; j < OUTC; j++) l[j] = fcb[j];
    for (int k = 0; k < HID; k++) {
        float p = g_pool[g * HID + k];
#pragma unroll
        for (int j = 0; j < OUTC; j++) l[j] = fmaf(p, fcw[k * OUTC + j], l[j]);
    }
    float mx = l[0];
#pragma unroll
    for (int j = 1; j < OUTC; j++) mx = fmaxf(mx, l[j]);
    float s = 0.f;
#pragma unroll
    for (int j = 0; j < OUTC; j++) s += expf(l[j] - mx);
    float lse = mx + logf(s);
#pragma unroll
    for (int j = 0; j < OUTC; j++) out[g * OUTC + j] = l[j] - lse;
}

// ---------------- launch ----------------
extern "C" void kernel_launch(void* const* d_in, const int* in_sizes, int n_in,
                              void* d_out, int out_size) {
    const float* x      = (const float*)d_in[0];
    const int*   ei_raw = (const int*)d_in[1];
    const int*   b_raw  = (const int*)d_in[2];
    const float* W1     = (const float*)d_in[3];
    const float* a_src1 = (const float*)d_in[4];
    const float* a_dst1 = (const float*)d_in[5];
    const float* b1     = (const float*)d_in[6];
    const float* W2     = (const float*)d_in[7];
    const float* a_src2 = (const float*)d_in[8];
    const float* a_dst2 = (const float*)d_in[9];
    const float* b2     = (const float*)d_in[10];
    const float* fcw    = (const float*)d_in[11];
    const float* fcb    = (const float*)d_in[12];
    float*       out    = (float*)d_out;

    void *p_h1b, *p_out1b, *p_h2b, *p_als1, *p_ald1, *p_als2, *p_ald2;
    cudaGetSymbolAddress(&p_h1b, g_h1b);
    cudaGetSymbolAddress(&p_out1b, g_out1b);
    cudaGetSymbolAddress(&p_h2b, g_h2b);
    cudaGetSymbolAddress(&p_als1, g_als1);
    cudaGetSymbolAddress(&p_ald1, g_ald1);
    cudaGetSymbolAddress(&p_als2, g_als2);
    cudaGetSymbolAddress(&p_ald2, g_ald2);

    // one-time stream/event creation (first call is the uncaptured correctness
    // run; later captured calls reuse them — no allocs during capture)
    static cudaStream_t s_aux = nullptr;
    static cudaEvent_t ev_fork = nullptr, ev_join = nullptr;
    if (s_aux == nullptr) {
        cudaStreamCreateWithFlags(&s_aux, cudaStreamNonBlocking);
        cudaEventCreateWithFlags(&ev_fork, cudaEventDisableTiming);
        cudaEventCreateWithFlags(&ev_join, cudaEventDisableTiming);
    }

    const int T = 256;
    const int gN  = (NN + T - 1) / T;
    const int gE  = (NE + T - 1) / T;
    const int gNw = (NN * 32 + T - 1) / T;   // warp per node
    const int gM  = (NN + 127) / 128;

    // ---- fork: CSR build chain on s_aux, concurrent with GEMM1 ----
    cudaEventRecord(ev_fork, 0);
    cudaStreamWaitEvent(s_aux, ev_fork, 0);
    prep_k<<<gN, T, 0, s_aux>>>(ei_raw);
    cvt_k<<<gE, T, 0, s_aux>>>(ei_raw, b_raw);
    scan_k<<<1, 1024, 0, s_aux>>>();
    place_k<<<gE, T, 0, s_aux>>>();
    cudaEventRecord(ev_join, s_aux);

    // ---- GAT layer 1: GEMM + fused attention logits ----
    mma_gemm_k<0><<<dim3(D1 / 64, gM), 256>>>(x, W1, (__nv_bfloat16*)p_h1b,
                                              a_src1, a_dst1,
                                              (float*)p_als1, (float*)p_ald1,
                                              HEADS, NN, D1, INC);

    // ---- join: aggregation needs both chains ----
    cudaStreamWaitEvent(0, ev_join, 0);
    agg1_k<<<gNw, T>>>(b1);

    // ---- GAT layer 2: GEMM (bf16 A) + fused logits, then aggregate+pool ----
    mma_gemm_k<1><<<dim3(HID / 64, gM), 256>>>(p_out1b, W2, (__nv_bfloat16*)p_h2b,
                                               a_src2, a_dst2,
                                               (float*)p_als2, (float*)p_ald2,
                                               1, NN, HID, D1);
    agg2_k<<<gNw, T>>>(b2);

    // ---- classifier ----
    cls_k<<<(NG + T - 1) / T, T>>>(fcw, fcb, out);
}